// round 16
// baseline (speedup 1.0000x reference)
#include <cuda_runtime.h>
#include <cuda_fp16.h>
#include <cstdint>

// ---------------------------------------------------------------------------
// Fused two-tower scorer, round 15: R10 frame (best measured: KC=32, W
// triple-buffered cp.async, TB=64, 512 thr, 2 CTAs/SM, fp16 m16n8k16)
// with the warp tile reshaped 16x64 -> 32x32: same 16 MMAs and 32 acc regs
// per warp-chunk, but 8 instead of 10 LDS.128 (square tile minimizes
// (m+n)/(m*n) operand traffic). Everything else byte-identical to R10.
// ---------------------------------------------------------------------------

#define NTHREADS 512
#define TB       64      // batch rows per CTA
#define LOUT     256     // latents (GEMM N)
#define KF       512     // features (GEMM K)
#define KC       32      // K chunk (elements) = 16 fp16 pairs per row
#define NCHUNK   32      // 16 chunks per tower x 2 towers
#define ASTU     16      // A smem row stride (uints), conflict-free
#define WSTU     16      // W smem row stride (uints)
#define ULST     264     // user-latent smem stride (halves)

// smem byte offsets
#define S_IDXU   0                       // 64 ints
#define S_IDXI   256
#define S_UB     512                     // 256 f32
#define S_IB     1536
#define S_PART   2560                    // 64 f32
#define S_ULAT   3584                    // 64 x 264 half = 33792
#define S_A      37376                   // A tiles, double buffered
#define A_BYTES  (TB * ASTU * 4)         // 4096
#define S_W      (S_A + 2 * A_BYTES)     // 45568, W triple buffered
#define W_BYTES  (LOUT * WSTU * 4)       // 16384
#define S_TOTAL  (S_W + 3 * W_BYTES)     // 94720 -> 2 CTAs/SM

// pre-converted, permuted fp16 weights, per-chunk contiguous:
// index = tower*65536 + ch*4096 + l*16 + pos;  pos = 4t + 2s + b for
// pair p = 8s + 4b + t  (k = ch*32 + 2p, 2p+1)
__device__ uint32_t wscr[2 * 16 * LOUT * 16];

// --------------------------- helpers ----------------------------------------

__device__ __forceinline__ void mma16(float* c, uint32_t a0, uint32_t a1,
                                      uint32_t a2, uint32_t a3,
                                      uint32_t b0, uint32_t b1) {
    asm volatile(
        "mma.sync.aligned.m16n8k16.row.col.f32.f16.f16.f32 "
        "{%0,%1,%2,%3}, {%4,%5,%6,%7}, {%8,%9}, {%0,%1,%2,%3};"
        : "+f"(c[0]), "+f"(c[1]), "+f"(c[2]), "+f"(c[3])
        : "r"(a0), "r"(a1), "r"(a2), "r"(a3), "r"(b0), "r"(b1));
}

__device__ __forceinline__ void cp16(uint32_t dst, const void* src) {
    asm volatile("cp.async.cg.shared.global [%0], [%1], 16;"
                 :: "r"(dst), "l"(src) : "memory");
}

__device__ __forceinline__ uint32_t h2u(__half2 h) {
    return *reinterpret_cast<uint32_t*>(&h);
}

// pos(p) = 4*(p&3) + 2*(p>>3) + ((p>>2)&1)
__device__ __forceinline__ int posof(int p) {
    return ((p & 3) << 2) | ((p >> 3) << 1) | ((p >> 2) & 1);
}

// W chunk c -> smem buffer c%3 (scratch already fp16 + permuted)
__device__ __forceinline__ void issue_w(int c, uint32_t sb, int tid) {
    const int tower = c >> 4, ch = c & 15, buf = c % 3;
    const uint32_t* src0 = wscr + tower * 65536 + ch * 4096;
    const uint32_t dst0 = sb + S_W + buf * W_BYTES;
    // 1024 16B segs / 512 thr = 2 per thread (contiguous)
#pragma unroll
    for (int i = 0; i < 2; i++) {
        int seg = tid + i * NTHREADS;
        cp16(dst0 + seg * 16, src0 + seg * 4);
    }
    asm volatile("cp.async.commit_group;" ::: "memory");
}

// A chunk: 64 rows x 8 float4 = 512 segs / 512 thr
__device__ __forceinline__ void ldg_a(float4* pref, const float* lut,
                                      const int* idx, int kc, int tid) {
    int row = tid >> 3, q = tid & 7;
    *pref = __ldg(reinterpret_cast<const float4*>(
        lut + (size_t)idx[row] * KF + kc + q * 4));
}

// store A chunk as fp16 pairs with permutation
__device__ __forceinline__ void sts_a(const float4* pref, char* smem, int c,
                                      int tid) {
    uint32_t* base = (uint32_t*)(smem + S_A + (c & 1) * A_BYTES);
    int row = tid >> 3, q = tid & 7;
    int p1 = 2 * q, p2 = 2 * q + 1;
    base[row * ASTU + posof(p1)] = h2u(__floats2half2_rn(pref->x, pref->y));
    base[row * ASTU + posof(p2)] = h2u(__floats2half2_rn(pref->z, pref->w));
}

// --------------------------- prep kernel ------------------------------------

__global__ void prep_kernel(const float* __restrict__ uW,
                            const float* __restrict__ iW) {
    int o = blockIdx.x * 256 + threadIdx.x;        // [0, 131072)
    int tower = o >> 16;
    int r = o & 65535;
    int ch = r >> 12;
    int l = (r >> 4) & (LOUT - 1);
    int pos = r & 15;
    int t = pos >> 2, s = (pos >> 1) & 1, b = pos & 1;
    int p = 8 * s + 4 * b + t;
    const float* W = (tower ? iW : uW) + (size_t)l * KF + ch * KC + 2 * p;
    wscr[o] = h2u(__floats2half2_rn(W[0], W[1]));
}

// --------------------------- main kernel ------------------------------------

__global__ void __launch_bounds__(NTHREADS, 2) towers_kernel(
    const int* __restrict__ x,
    const float* __restrict__ ulut, const float* __restrict__ ilut,
    const float* __restrict__ ubias, const float* __restrict__ ibias,
    float* __restrict__ out) {
    extern __shared__ char smem[];
    uint32_t sb;
    asm("{ .reg .u64 t; cvta.to.shared.u64 t, %1; cvt.u32.u64 %0, t; }"
        : "=r"(sb) : "l"(smem));
    const int tid  = threadIdx.x;
    const int lane = tid & 31;
    const int wid  = tid >> 5;
    const int wm   = wid & 1;        // 2 row groups of 32
    const int wn   = wid >> 1;       // 8 col groups of 32
    const int g    = lane >> 2;
    const int t    = lane & 3;

    int*   idxu = (int*)(smem + S_IDXU);
    int*   idxi = (int*)(smem + S_IDXI);
    float* ubS  = (float*)(smem + S_UB);
    float* ibS  = (float*)(smem + S_IB);
    float* part = (float*)(smem + S_PART);
    __half* ulat = (__half*)(smem + S_ULAT);

    if (tid < LOUT) {
        ubS[tid] = ubias[tid];
        ibS[tid] = ibias[tid];
    }
    if (tid < TB) {
        part[tid] = 0.f;
        int gg = blockIdx.x * TB + tid;
        idxu[tid] = x[2 * gg];
        idxi[tid] = x[2 * gg + 1];
    }
    __syncthreads();

    issue_w(0, sb, tid);
    issue_w(1, sb, tid);

    float4 pref;
    ldg_a(&pref, ulut, idxu, 0, tid);

    float acc[2][4][4];              // [msub][nsub][frag] = 32 regs
#pragma unroll
    for (int m = 0; m < 2; m++)
#pragma unroll
        for (int j = 0; j < 4; j++)
#pragma unroll
            for (int i = 0; i < 4; i++) acc[m][j][i] = 0.f;

    const int r0 = wm * 32 + g;      // fragment rows
    const int r1 = r0 + 8;
    const int r2 = r0 + 16;
    const int r3 = r0 + 24;

    for (int c = 0; c < NCHUNK; c++) {
        // 1. store prefetched A; buffer (c&1)'s last reader MMA(c-2) is
        //    CTA-wide complete past sync(c-1).
        sts_a(&pref, smem, c, tid);

        // 2. prefetch next A chunk
        if (c + 1 < NCHUNK) {
            int c2 = c + 1;
            bool t2 = (c2 >= NCHUNK / 2);
            ldg_a(&pref, t2 ? ilut : ulut, t2 ? idxi : idxu,
                  (c2 & 15) * KC, tid);
        }

        // 3. ensure W chunk c landed (newest outstanding group is c+1)
        if (c <= NCHUNK - 3)
            asm volatile("cp.async.wait_group 1;" ::: "memory");
        else
            asm volatile("cp.async.wait_group 0;" ::: "memory");
        __syncthreads();

        // 4. refill W pipeline
        if (c + 2 < NCHUNK) issue_w(c + 2, sb, tid);

        // 5. MMA on chunk c: 32x32 warp tile, 4 A + 4 B LDS.128, 16 MMAs
        const uint32_t* A  = (const uint32_t*)(smem + S_A + (c & 1) * A_BYTES);
        const uint32_t* Bs = (const uint32_t*)(smem + S_W + (c % 3) * W_BYTES);

        uint4 a0 = *(const uint4*)(A + r0 * ASTU + 4 * t);
        uint4 a1 = *(const uint4*)(A + r1 * ASTU + 4 * t);
        uint4 a2 = *(const uint4*)(A + r2 * ASTU + 4 * t);
        uint4 a3 = *(const uint4*)(A + r3 * ASTU + 4 * t);
#pragma unroll
        for (int j = 0; j < 4; j++) {
            const int n0 = wn * 32 + j * 8 + g;
            uint4 bv = *(const uint4*)(Bs + n0 * WSTU + 4 * t);
            // kstep 0: x,y ; kstep 1: z,w
            mma16(acc[0][j], a0.x, a1.x, a0.y, a1.y, bv.x, bv.y);
            mma16(acc[1][j], a2.x, a3.x, a2.y, a3.y, bv.x, bv.y);
            mma16(acc[0][j], a0.z, a1.z, a0.w, a1.w, bv.z, bv.w);
            mma16(acc[1][j], a2.z, a3.z, a2.w, a3.w, bv.z, bv.w);
        }

        // 6. user-tower epilogue: bias + relu -> fp16 smem, reset acc
        if (c == NCHUNK / 2 - 1) {
#pragma unroll
            for (int m = 0; m < 2; m++) {
                const int ra = wm * 32 + m * 16 + g;
                const int rb = ra + 8;
#pragma unroll
                for (int j = 0; j < 4; j++) {
                    const int c0 = wn * 32 + j * 8 + 2 * t;
                    float u0 = fmaxf(acc[m][j][0] + ubS[c0],     0.f);
                    float u1 = fmaxf(acc[m][j][1] + ubS[c0 + 1], 0.f);
                    float u2 = fmaxf(acc[m][j][2] + ubS[c0],     0.f);
                    float u3 = fmaxf(acc[m][j][3] + ubS[c0 + 1], 0.f);
                    *(__half2*)(ulat + ra * ULST + c0) =
                        __floats2half2_rn(u0, u1);
                    *(__half2*)(ulat + rb * ULST + c0) =
                        __floats2half2_rn(u2, u3);
                    acc[m][j][0] = acc[m][j][1] = 0.f;
                    acc[m][j][2] = acc[m][j][3] = 0.f;
                }
            }
        }
    }

    // item-tower epilogue: bias+relu, product with user latent, row-reduce
#pragma unroll
    for (int m = 0; m < 2; m++) {
        const int ra = wm * 32 + m * 16 + g;
        const int rb = ra + 8;
        float s0 = 0.f, s1 = 0.f;
#pragma unroll
        for (int j = 0; j < 4; j++) {
            const int c0 = wn * 32 + j * 8 + 2 * t;
            float v0 = fmaxf(acc[m][j][0] + ibS[c0],     0.f);
            float v1 = fmaxf(acc[m][j][1] + ibS[c0 + 1], 0.f);
            float v2 = fmaxf(acc[m][j][2] + ibS[c0],     0.f);
            float v3 = fmaxf(acc[m][j][3] + ibS[c0 + 1], 0.f);
            float2 u01 = __half22float2(*(__half2*)(ulat + ra * ULST + c0));
            float2 u23 = __half22float2(*(__half2*)(ulat + rb * ULST + c0));
            s0 = fmaf(u01.x, v0, fmaf(u01.y, v1, s0));
            s1 = fmaf(u23.x, v2, fmaf(u23.y, v3, s1));
        }
        s0 += __shfl_xor_sync(0xffffffffu, s0, 1);
        s0 += __shfl_xor_sync(0xffffffffu, s0, 2);
        s1 += __shfl_xor_sync(0xffffffffu, s1, 1);
        s1 += __shfl_xor_sync(0xffffffffu, s1, 2);
        if (t == 0) {
            atomicAdd(&part[ra], s0);
            atomicAdd(&part[rb], s1);
        }
    }
    __syncthreads();

    if (tid < TB) out[blockIdx.x * TB + tid] = part[tid];
}

// --------------------------- launch -----------------------------------------

extern "C" void kernel_launch(void* const* d_in, const int* in_sizes, int n_in,
                              void* d_out, int out_size) {
    const int* x      = (const int*)d_in[0];
    const float* ulut = (const float*)d_in[1];
    const float* ilut = (const float*)d_in[2];
    const float* uW   = (const float*)d_in[3];
    const float* ub   = (const float*)d_in[4];
    const float* iW   = (const float*)d_in[5];
    const float* ib   = (const float*)d_in[6];
    float* out        = (float*)d_out;

    prep_kernel<<<2 * 16 * LOUT * 16 / 256, 256>>>(uW, iW);

    cudaFuncSetAttribute(towers_kernel,
                         cudaFuncAttributeMaxDynamicSharedMemorySize, S_TOTAL);
    int grid = out_size / TB;   // 16384 / 64 = 256
    towers_kernel<<<grid, NTHREADS, S_TOTAL>>>(x, ulut, ilut, ub, ib, out);
}

// round 17
// speedup vs baseline: 1.0960x; 1.0960x over previous
#include <cuda_runtime.h>
#include <cuda_fp16.h>
#include <cstdint>

// ---------------------------------------------------------------------------
// Fused two-tower scorer, round 16: exact R10 (best measured, 51.2us) with
// two surgical changes to kill its 33.9% ALU overhead:
//   - W buffers 3 -> 4 (c&3): power-of-2 cycle, still 2 CTAs/SM (108.5 KB)
//   - #pragma unroll 4 on the chunk loop: all buffer bases become
//     compile-time constants per unrolled copy.
// fp16 m16n8k16, TB=64, 512 thr, warp tile 16x64, KC=32.
// ---------------------------------------------------------------------------

#define NTHREADS 512
#define TB       64      // batch rows per CTA
#define LOUT     256     // latents (GEMM N)
#define KF       512     // features (GEMM K)
#define KC       32      // K chunk (elements) = 16 fp16 pairs per row
#define NCHUNK   32      // 16 chunks per tower x 2 towers
#define ASTU     16      // A smem row stride (uints), conflict-free
#define WSTU     16      // W smem row stride (uints)
#define ULST     264     // user-latent smem stride (halves)

// smem byte offsets
#define S_IDXU   0                       // 64 ints
#define S_IDXI   256
#define S_UB     512                     // 256 f32
#define S_IB     1536
#define S_PART   2560                    // 64 f32
#define S_ULAT   3584                    // 64 x 264 half = 33792
#define S_A      37376                   // A tiles, double buffered
#define A_BYTES  (TB * ASTU * 4)         // 4096
#define S_W      (S_A + 2 * A_BYTES)     // 45568, W quad buffered
#define W_BYTES  (LOUT * WSTU * 4)       // 16384
#define S_TOTAL  (S_W + 4 * W_BYTES)     // 111104 -> 2 CTAs/SM

// pre-converted, permuted fp16 weights, per-chunk contiguous:
// index = tower*65536 + ch*4096 + l*16 + pos;  pos = 4t + 2s + b for
// pair p = 8s + 4b + t  (k = ch*32 + 2p, 2p+1)
__device__ uint32_t wscr[2 * 16 * LOUT * 16];

// --------------------------- helpers ----------------------------------------

__device__ __forceinline__ void mma16(float* c, uint32_t a0, uint32_t a1,
                                      uint32_t a2, uint32_t a3,
                                      uint32_t b0, uint32_t b1) {
    asm volatile(
        "mma.sync.aligned.m16n8k16.row.col.f32.f16.f16.f32 "
        "{%0,%1,%2,%3}, {%4,%5,%6,%7}, {%8,%9}, {%0,%1,%2,%3};"
        : "+f"(c[0]), "+f"(c[1]), "+f"(c[2]), "+f"(c[3])
        : "r"(a0), "r"(a1), "r"(a2), "r"(a3), "r"(b0), "r"(b1));
}

__device__ __forceinline__ void cp16(uint32_t dst, const void* src) {
    asm volatile("cp.async.cg.shared.global [%0], [%1], 16;"
                 :: "r"(dst), "l"(src) : "memory");
}

__device__ __forceinline__ uint32_t h2u(__half2 h) {
    return *reinterpret_cast<uint32_t*>(&h);
}

// pos(p) = 4*(p&3) + 2*(p>>3) + ((p>>2)&1)
__device__ __forceinline__ int posof(int p) {
    return ((p & 3) << 2) | ((p >> 3) << 1) | ((p >> 2) & 1);
}

// W chunk c -> smem buffer c&3 (scratch already fp16 + permuted)
__device__ __forceinline__ void issue_w(int c, uint32_t sb, int tid) {
    const int tower = c >> 4, ch = c & 15, buf = c & 3;
    const uint32_t* src0 = wscr + tower * 65536 + ch * 4096;
    const uint32_t dst0 = sb + S_W + buf * W_BYTES;
    // 1024 16B segs / 512 thr = 2 per thread (contiguous)
#pragma unroll
    for (int i = 0; i < 2; i++) {
        int seg = tid + i * NTHREADS;
        cp16(dst0 + seg * 16, src0 + seg * 4);
    }
    asm volatile("cp.async.commit_group;" ::: "memory");
}

// A chunk: 64 rows x 8 float4 = 512 segs / 512 thr
__device__ __forceinline__ void ldg_a(float4* pref, const float* lut,
                                      const int* idx, int kc, int tid) {
    int row = tid >> 3, q = tid & 7;
    *pref = __ldg(reinterpret_cast<const float4*>(
        lut + (size_t)idx[row] * KF + kc + q * 4));
}

// store A chunk as fp16 pairs with permutation
__device__ __forceinline__ void sts_a(const float4* pref, char* smem, int c,
                                      int tid) {
    uint32_t* base = (uint32_t*)(smem + S_A + (c & 1) * A_BYTES);
    int row = tid >> 3, q = tid & 7;
    int p1 = 2 * q, p2 = 2 * q + 1;
    base[row * ASTU + posof(p1)] = h2u(__floats2half2_rn(pref->x, pref->y));
    base[row * ASTU + posof(p2)] = h2u(__floats2half2_rn(pref->z, pref->w));
}

// --------------------------- prep kernel ------------------------------------

__global__ void prep_kernel(const float* __restrict__ uW,
                            const float* __restrict__ iW) {
    int o = blockIdx.x * 256 + threadIdx.x;        // [0, 131072)
    int tower = o >> 16;
    int r = o & 65535;
    int ch = r >> 12;
    int l = (r >> 4) & (LOUT - 1);
    int pos = r & 15;
    int t = pos >> 2, s = (pos >> 1) & 1, b = pos & 1;
    int p = 8 * s + 4 * b + t;
    const float* W = (tower ? iW : uW) + (size_t)l * KF + ch * KC + 2 * p;
    wscr[o] = h2u(__floats2half2_rn(W[0], W[1]));
}

// --------------------------- main kernel ------------------------------------

__global__ void __launch_bounds__(NTHREADS, 2) towers_kernel(
    const int* __restrict__ x,
    const float* __restrict__ ulut, const float* __restrict__ ilut,
    const float* __restrict__ ubias, const float* __restrict__ ibias,
    float* __restrict__ out) {
    extern __shared__ char smem[];
    uint32_t sb;
    asm("{ .reg .u64 t; cvta.to.shared.u64 t, %1; cvt.u32.u64 %0, t; }"
        : "=r"(sb) : "l"(smem));
    const int tid  = threadIdx.x;
    const int lane = tid & 31;
    const int wid  = tid >> 5;
    const int wm   = wid & 3;        // 4 row groups of 16
    const int wn   = wid >> 2;       // 4 col groups of 64
    const int g    = lane >> 2;
    const int t    = lane & 3;

    int*   idxu = (int*)(smem + S_IDXU);
    int*   idxi = (int*)(smem + S_IDXI);
    float* ubS  = (float*)(smem + S_UB);
    float* ibS  = (float*)(smem + S_IB);
    float* part = (float*)(smem + S_PART);
    __half* ulat = (__half*)(smem + S_ULAT);

    if (tid < LOUT) {
        ubS[tid] = ubias[tid];
        ibS[tid] = ibias[tid];
    }
    if (tid < TB) {
        part[tid] = 0.f;
        int gg = blockIdx.x * TB + tid;
        idxu[tid] = x[2 * gg];
        idxi[tid] = x[2 * gg + 1];
    }
    __syncthreads();

    issue_w(0, sb, tid);
    issue_w(1, sb, tid);

    float4 pref;
    ldg_a(&pref, ulut, idxu, 0, tid);

    float acc[8][4];
#pragma unroll
    for (int nt = 0; nt < 8; nt++)
#pragma unroll
        for (int i = 0; i < 4; i++) acc[nt][i] = 0.f;

    const int rlo = wm * 16 + g;         // fragment rows
    const int rhi = wm * 16 + 8 + g;

#pragma unroll 4
    for (int c = 0; c < NCHUNK; c++) {
        // 1. store prefetched A; buffer (c&1)'s last reader MMA(c-2) is
        //    CTA-wide complete past sync(c-1).
        sts_a(&pref, smem, c, tid);

        // 2. prefetch next A chunk
        if (c + 1 < NCHUNK) {
            int c2 = c + 1;
            bool t2 = (c2 >= NCHUNK / 2);
            ldg_a(&pref, t2 ? ilut : ulut, t2 ? idxi : idxu,
                  (c2 & 15) * KC, tid);
        }

        // 3. ensure W chunk c landed (newest outstanding group is c+1)
        if (c <= NCHUNK - 3)
            asm volatile("cp.async.wait_group 1;" ::: "memory");
        else
            asm volatile("cp.async.wait_group 0;" ::: "memory");
        __syncthreads();

        // 4. refill W pipeline (buffer (c+2)&3's last reader was chunk c-2)
        if (c + 2 < NCHUNK) issue_w(c + 2, sb, tid);

        // 5. MMA on chunk c: 2 k-steps, one LDS.128 per row covers both
        const uint32_t* A  = (const uint32_t*)(smem + S_A + (c & 1) * A_BYTES);
        const uint32_t* Bs = (const uint32_t*)(smem + S_W + (c & 3) * W_BYTES);

        uint4 alo = *(const uint4*)(A + rlo * ASTU + 4 * t);
        uint4 ahi = *(const uint4*)(A + rhi * ASTU + 4 * t);
#pragma unroll
        for (int ntb = 0; ntb < 4; ntb++) {      // 2 n-tiles at a time
            uint4 bv0, bv1;
            {
                const int n0 = wn * 64 + (ntb * 2) * 8 + g;
                const int n1 = n0 + 8;
                bv0 = *(const uint4*)(Bs + n0 * WSTU + 4 * t);
                bv1 = *(const uint4*)(Bs + n1 * WSTU + 4 * t);
            }
            // kstep 0: x,y ; kstep 1: z,w
            mma16(acc[ntb * 2],     alo.x, ahi.x, alo.y, ahi.y, bv0.x, bv0.y);
            mma16(acc[ntb * 2 + 1], alo.x, ahi.x, alo.y, ahi.y, bv1.x, bv1.y);
            mma16(acc[ntb * 2],     alo.z, ahi.z, alo.w, ahi.w, bv0.z, bv0.w);
            mma16(acc[ntb * 2 + 1], alo.z, ahi.z, alo.w, ahi.w, bv1.z, bv1.w);
        }

        // 6. user-tower epilogue: bias + relu -> fp16 smem, reset acc
        if (c == NCHUNK / 2 - 1) {
#pragma unroll
            for (int nt = 0; nt < 8; nt++) {
                const int c0 = wn * 64 + nt * 8 + 2 * t;
                float u0 = fmaxf(acc[nt][0] + ubS[c0],     0.f);
                float u1 = fmaxf(acc[nt][1] + ubS[c0 + 1], 0.f);
                float u2 = fmaxf(acc[nt][2] + ubS[c0],     0.f);
                float u3 = fmaxf(acc[nt][3] + ubS[c0 + 1], 0.f);
                *(__half2*)(ulat + rlo * ULST + c0) = __floats2half2_rn(u0, u1);
                *(__half2*)(ulat + rhi * ULST + c0) = __floats2half2_rn(u2, u3);
                acc[nt][0] = acc[nt][1] = acc[nt][2] = acc[nt][3] = 0.f;
            }
        }
    }

    // item-tower epilogue: bias+relu, product with user latent, row-reduce
    {
        float s0 = 0.f, s1 = 0.f;
#pragma unroll
        for (int nt = 0; nt < 8; nt++) {
            const int c0 = wn * 64 + nt * 8 + 2 * t;
            float v0 = fmaxf(acc[nt][0] + ibS[c0],     0.f);
            float v1 = fmaxf(acc[nt][1] + ibS[c0 + 1], 0.f);
            float v2 = fmaxf(acc[nt][2] + ibS[c0],     0.f);
            float v3 = fmaxf(acc[nt][3] + ibS[c0 + 1], 0.f);
            float2 u01 = __half22float2(*(__half2*)(ulat + rlo * ULST + c0));
            float2 u23 = __half22float2(*(__half2*)(ulat + rhi * ULST + c0));
            s0 = fmaf(u01.x, v0, fmaf(u01.y, v1, s0));
            s1 = fmaf(u23.x, v2, fmaf(u23.y, v3, s1));
        }
        s0 += __shfl_xor_sync(0xffffffffu, s0, 1);
        s0 += __shfl_xor_sync(0xffffffffu, s0, 2);
        s1 += __shfl_xor_sync(0xffffffffu, s1, 1);
        s1 += __shfl_xor_sync(0xffffffffu, s1, 2);
        if (t == 0) {
            atomicAdd(&part[rlo], s0);
            atomicAdd(&part[rhi], s1);
        }
    }
    __syncthreads();

    if (tid < TB) out[blockIdx.x * TB + tid] = part[tid];
}

// --------------------------- launch -----------------------------------------

extern "C" void kernel_launch(void* const* d_in, const int* in_sizes, int n_in,
                              void* d_out, int out_size) {
    const int* x      = (const int*)d_in[0];
    const float* ulut = (const float*)d_in[1];
    const float* ilut = (const float*)d_in[2];
    const float* uW   = (const float*)d_in[3];
    const float* ub   = (const float*)d_in[4];
    const float* iW   = (const float*)d_in[5];
    const float* ib   = (const float*)d_in[6];
    float* out        = (float*)d_out;

    prep_kernel<<<2 * 16 * LOUT * 16 / 256, 256>>>(uW, iW);

    cudaFuncSetAttribute(towers_kernel,
                         cudaFuncAttributeMaxDynamicSharedMemorySize, S_TOTAL);
    int grid = out_size / TB;   // 16384 / 64 = 256
    towers_kernel<<<grid, NTHREADS, S_TOTAL>>>(x, ulut, ilut, ub, ib, out);
}